// round 1
// baseline (speedup 1.0000x reference)
#include <cuda_runtime.h>
#include <cstdint>

#define DM   1024
#define NTOK 4096

// ---------------- scratch (static device allocs are the sanctioned path) ----
__device__ float g_Xt[(size_t)NTOK * DM];   // X^T  [N, d]
__device__ float g_Q [(size_t)NTOK * DM];
__device__ float g_K [(size_t)NTOK * DM];
__device__ float g_V [(size_t)NTOK * DM];
__device__ float g_RH[(size_t)NTOK * DM];   // (X W_V) W_O
__device__ float g_S [(size_t)NTOK * NTOK]; // scores / attention weights
__device__ float g_X2[(size_t)NTOK * DM];   // Xt + A@RH
__device__ float g_H [(size_t)NTOK * DM];   // relu hidden

#define NEG_INF (-__int_as_float(0x7f800000))

// ---------------- transpose X [DM, NTOK] -> Xt [NTOK, DM] -------------------
__global__ __launch_bounds__(256)
void transpose_kernel(const float* __restrict__ X, float* __restrict__ Xt) {
    __shared__ float tile[32][33];
    int x = blockIdx.x * 32 + threadIdx.x;   // along NTOK
    int y = blockIdx.y * 32 + threadIdx.y;   // along DM
#pragma unroll
    for (int i = 0; i < 32; i += 8)
        tile[threadIdx.y + i][threadIdx.x] = X[(size_t)(y + i) * NTOK + x];
    __syncthreads();
    int tx = blockIdx.y * 32 + threadIdx.x;  // along DM
    int ty = blockIdx.x * 32 + threadIdx.y;  // along NTOK
#pragma unroll
    for (int i = 0; i < 32; i += 8)
        Xt[(size_t)(ty + i) * DM + tx] = tile[threadIdx.x][threadIdx.y + i];
}

// ---------------- generic fp32 SGEMM: 128x128x8, 8x8 microtile --------------
// TB:     0 -> C = A[M,K] * B[K,N]      (both row-major)
//         1 -> C = A[M,K] * B[N,K]^T    (B row-major, accessed [n,k])
// EPI:    0 -> C = acc
//         1 -> C = acc + R               (R same shape as C)
//         2 -> C = relu(acc)
//         3 -> C_T[c*NTOK + r] = acc + R (transposed store, final output)
// CMASK:  1 -> causal mask (c > r -> -inf), early-exit fully-masked blocks
// CKLIM:  1 -> bound k-loop at row-block end (A has zeros beyond)
template<int TB, int EPI, int CMASK, int CKLIM>
__global__ __launch_bounds__(256)
void gemm128(const float* __restrict__ A, const float* __restrict__ B,
             const float* __restrict__ R, float* __restrict__ C,
             int M, int N, int K)
{
    const int bm = blockIdx.y, bn = blockIdx.x;
    const int row0 = bm * 128, col0 = bn * 128;
    const int tid = threadIdx.x;

    if (CMASK) {
        if (col0 > row0 + 127) {
            // fully above the diagonal: fill -inf and bail
            int r  = tid >> 5;
            int c4 = (tid & 31) * 4;
            float4 v = make_float4(NEG_INF, NEG_INF, NEG_INF, NEG_INF);
#pragma unroll
            for (int i = 0; i < 128; i += 8)
                *(float4*)&C[(size_t)(row0 + r + i) * N + col0 + c4] = v;
            return;
        }
    }

    __shared__ __align__(16) float As[8][128];
    __shared__ __align__(16) float Bs[8][128];

    float acc[8][8] = {};

    int kEnd = K;
    if (CKLIM) { int lim = row0 + 128; kEnd = (lim < K) ? lim : K; }

    const int ar = tid >> 1;          // 0..127 : m (or n for TB) index in tile
    const int ac = (tid & 1) * 4;     // 0 or 4 : k offset
    const int br = tid >> 5;          // 0..7   : k index (NN B load)
    const int bc = (tid & 31) * 4;    // 0..124 : n offset

    const int tr = (tid >> 4) * 8;    // microtile row
    const int tc = (tid & 15) * 8;    // microtile col

    for (int k0 = 0; k0 < kEnd; k0 += 8) {
        float4 a = *(const float4*)&A[(size_t)(row0 + ar) * K + k0 + ac];
        As[ac + 0][ar] = a.x; As[ac + 1][ar] = a.y;
        As[ac + 2][ar] = a.z; As[ac + 3][ar] = a.w;
        if (TB) {
            float4 b = *(const float4*)&B[(size_t)(col0 + ar) * K + k0 + ac];
            Bs[ac + 0][ar] = b.x; Bs[ac + 1][ar] = b.y;
            Bs[ac + 2][ar] = b.z; Bs[ac + 3][ar] = b.w;
        } else {
            float4 b = *(const float4*)&B[(size_t)(k0 + br) * N + col0 + bc];
            Bs[br][bc + 0] = b.x; Bs[br][bc + 1] = b.y;
            Bs[br][bc + 2] = b.z; Bs[br][bc + 3] = b.w;
        }
        __syncthreads();
#pragma unroll
        for (int kk = 0; kk < 8; kk++) {
            float4 a0 = *(const float4*)&As[kk][tr];
            float4 a1 = *(const float4*)&As[kk][tr + 4];
            float4 b0 = *(const float4*)&Bs[kk][tc];
            float4 b1 = *(const float4*)&Bs[kk][tc + 4];
            float ra[8] = {a0.x, a0.y, a0.z, a0.w, a1.x, a1.y, a1.z, a1.w};
            float rb[8] = {b0.x, b0.y, b0.z, b0.w, b1.x, b1.y, b1.z, b1.w};
#pragma unroll
            for (int i = 0; i < 8; i++)
#pragma unroll
                for (int j = 0; j < 8; j++)
                    acc[i][j] = fmaf(ra[i], rb[j], acc[i][j]);
        }
        __syncthreads();
    }

#pragma unroll
    for (int i = 0; i < 8; i++) {
        int r = row0 + tr + i;
#pragma unroll
        for (int j = 0; j < 8; j++) {
            int c = col0 + tc + j;
            float v = acc[i][j];
            if (CMASK && c > r) v = NEG_INF;
            if (EPI == 1) v += R[(size_t)r * N + c];
            if (EPI == 2) v = fmaxf(v, 0.f);
            if (EPI == 3) {
                C[(size_t)c * NTOK + r] = v + R[(size_t)r * N + c];
            } else {
                C[(size_t)r * N + c] = v;
            }
        }
    }
}

// ---------------- row-wise causal softmax, in place -------------------------
__global__ __launch_bounds__(256)
void softmax_rows(float* __restrict__ S) {
    const int row = blockIdx.x;
    const int len = row + 1;
    float* p = S + (size_t)row * NTOK;
    __shared__ float red[256];
    const int tid = threadIdx.x;

    float m = NEG_INF;
    for (int j = tid; j < len; j += 256) m = fmaxf(m, p[j]);
    red[tid] = m; __syncthreads();
    for (int s = 128; s > 0; s >>= 1) {
        if (tid < s) red[tid] = fmaxf(red[tid], red[tid + s]);
        __syncthreads();
    }
    m = red[0]; __syncthreads();

    float sum = 0.f;
    for (int j = tid; j < len; j += 256) {
        float e = expf(p[j] - m);
        p[j] = e;
        sum += e;
    }
    red[tid] = sum; __syncthreads();
    for (int s = 128; s > 0; s >>= 1) {
        if (tid < s) red[tid] += red[tid + s];
        __syncthreads();
    }
    float inv = 1.f / red[0];
    for (int j = tid; j < len; j += 256) p[j] *= inv;

    // zero the masked tail up to this row-block's boundary so the k-bounded
    // A@RH GEMM reads exact zeros there
    int blockEnd = ((row >> 7) + 1) << 7;
    for (int j = len + tid; j < blockEnd; j += 256) p[j] = 0.f;
}

// ---------------- driver -----------------------------------------------------
extern "C" void kernel_launch(void* const* d_in, const int* in_sizes, int n_in,
                              void* d_out, int out_size) {
    (void)in_sizes; (void)n_in; (void)out_size;
    const float* X      = (const float*)d_in[0];
    const float* W_Q    = (const float*)d_in[1];
    const float* W_K    = (const float*)d_in[2];
    const float* W_V    = (const float*)d_in[3];
    const float* W_O    = (const float*)d_in[4];
    const float* mlp_in = (const float*)d_in[5];
    const float* mlp_out= (const float*)d_in[6];
    float* out = (float*)d_out;

    float *Xt, *Q, *K, *V, *RH, *S, *X2, *H;
    cudaGetSymbolAddress((void**)&Xt, g_Xt);
    cudaGetSymbolAddress((void**)&Q,  g_Q);
    cudaGetSymbolAddress((void**)&K,  g_K);
    cudaGetSymbolAddress((void**)&V,  g_V);
    cudaGetSymbolAddress((void**)&RH, g_RH);
    cudaGetSymbolAddress((void**)&S,  g_S);
    cudaGetSymbolAddress((void**)&X2, g_X2);
    cudaGetSymbolAddress((void**)&H,  g_H);

    // 1) Xt = X^T
    transpose_kernel<<<dim3(NTOK / 32, DM / 32), dim3(32, 8)>>>(X, Xt);

    dim3 blk(256);
    dim3 grid_d(DM / 128, NTOK / 128);    // [4096 x 1024] outputs
    dim3 grid_s(NTOK / 128, NTOK / 128);  // [4096 x 4096] scores

    // 2) Q, K, V projections
    gemm128<0,0,0,0><<<grid_d, blk>>>(Xt, W_Q, nullptr, Q,  NTOK, DM, DM);
    gemm128<0,0,0,0><<<grid_d, blk>>>(Xt, W_K, nullptr, K,  NTOK, DM, DM);
    gemm128<0,0,0,0><<<grid_d, blk>>>(Xt, W_V, nullptr, V,  NTOK, DM, DM);
    // 3) RH = V @ W_O
    gemm128<0,0,0,0><<<grid_d, blk>>>(V,  W_O, nullptr, RH, NTOK, DM, DM);
    // 4) scores = Q @ K^T with causal mask (upper tiles skipped)
    gemm128<1,0,1,0><<<grid_s, blk>>>(Q, K, nullptr, S, NTOK, NTOK, DM);
    // 5) softmax rows
    softmax_rows<<<NTOK, 256>>>(S);
    // 6) X2 = Xt + A @ RH   (k-loop bounded by causality)
    gemm128<0,1,0,1><<<grid_d, blk>>>(S, RH, Xt, X2, NTOK, DM, NTOK);
    // 7) H = relu(X2 @ mlp_in)
    gemm128<0,2,0,0><<<grid_d, blk>>>(X2, mlp_in, nullptr, H, NTOK, DM, DM);
    // 8) out = (X2 + H @ mlp_out)^T
    gemm128<0,3,0,0><<<grid_d, blk>>>(H, mlp_out, X2, out, NTOK, DM, DM);
}

// round 4
// speedup vs baseline: 2.1148x; 2.1148x over previous
#include <cuda_runtime.h>
#include <cuda_bf16.h>
#include <cstdint>
#include <cstddef>

#define DM   1024
#define NTOK 4096

typedef __nv_bfloat16 bf16;

// ---------------- scratch ----------------------------------------------------
__device__ float g_Xt [(size_t)NTOK * DM];          // X^T fp32 (residual)
__device__ bf16  g_Xth[(size_t)NTOK * DM];
__device__ bf16  g_Xtl[(size_t)NTOK * DM];
__device__ bf16  g_Wth[(size_t)6 * DM * DM];        // W^T hi
__device__ bf16  g_Wtl[(size_t)6 * DM * DM];        // W^T lo
__device__ bf16  g_Qh [(size_t)NTOK * DM];
__device__ bf16  g_Ql [(size_t)NTOK * DM];
__device__ bf16  g_Kh [(size_t)NTOK * DM];
__device__ bf16  g_Kl [(size_t)NTOK * DM];
__device__ bf16  g_Vh [(size_t)NTOK * DM];
__device__ bf16  g_Vl [(size_t)NTOK * DM];
__device__ bf16  g_RHth[(size_t)DM * NTOK];         // (V W_O)^T hi   [dm][tok]
__device__ bf16  g_RHtl[(size_t)DM * NTOK];
__device__ float g_S  [(size_t)NTOK * NTOK];        // raw scores fp32
__device__ bf16  g_Ah [(size_t)NTOK * NTOK];
__device__ bf16  g_Al [(size_t)NTOK * NTOK];
__device__ float g_X2 [(size_t)NTOK * DM];          // fp32 (residual)
__device__ bf16  g_X2h[(size_t)NTOK * DM];
__device__ bf16  g_X2l[(size_t)NTOK * DM];
__device__ bf16  g_Hh [(size_t)NTOK * DM];
__device__ bf16  g_Hl [(size_t)NTOK * DM];

#define NEG_INF (-__int_as_float(0x7f800000))

// ---------------- small helpers ----------------------------------------------
__device__ __forceinline__ uint32_t smem_u32(const void* p) {
    uint32_t a;
    asm("{ .reg .u64 t; cvta.to.shared.u64 t, %1; cvt.u32.u64 %0, t; }"
        : "=r"(a) : "l"(p));
    return a;
}

#define CP16(d, p) \
    asm volatile("cp.async.cg.shared.global [%0], [%1], 16;" :: "r"(d), "l"(p) : "memory")
#define CP_COMMIT()  asm volatile("cp.async.commit_group;" ::: "memory")
#define CP_WAIT1()   asm volatile("cp.async.wait_group 1;" ::: "memory")
#define CP_WAIT0()   asm volatile("cp.async.wait_group 0;" ::: "memory")

__device__ __forceinline__ void mma16816(float* c, const uint32_t* a, const uint32_t* b) {
    asm volatile(
        "mma.sync.aligned.m16n8k16.row.col.f32.bf16.bf16.f32 "
        "{%0,%1,%2,%3}, {%4,%5,%6,%7}, {%8,%9}, {%0,%1,%2,%3};"
        : "+f"(c[0]), "+f"(c[1]), "+f"(c[2]), "+f"(c[3])
        : "r"(a[0]), "r"(a[1]), "r"(a[2]), "r"(a[3]), "r"(b[0]), "r"(b[1]));
}

__device__ __forceinline__ void split2(float v, bf16& h, bf16& l) {
    h = __float2bfloat16_rn(v);
    l = __float2bfloat16_rn(v - __bfloat162float(h));
}

// ---------------- bf16-split GEMM (mma.sync, 2-stage cp.async pipeline) ------
// C[M, Ntot] = (Ah+Al)[M,Ktot] @ (Bh+Bl)[Ntot,Ktot]^T   (both K-major, ld = Ktot)
// CTA tile 128x128, warp tile 64x32, K-chunk 64.
// EPI: 0  Cf = acc (fp32)
//      1  Ch/Cl = split(acc)
//      2  Ch/Cl = split(relu(acc))
//      3  Cf = acc + R ; Ch/Cl = split(Cf)
//      4  transposed: Ch/Cl[c*ldC + r] = split(acc)
//      5  transposed: Cf[c*ldC + r] = acc + R
// CMASK: skip CTA tiles fully above causal diagonal
// CKLIM: K-loop bounded to row0+128 (A rows have zeros beyond)

#define TILE_B   18432               // 128 rows * 144B (36 words, 64 bf16 + pad)
#define STAGE_B  (4 * TILE_B)        // Ah | Al | Bh | Bl
#define DSMEM    (2 * STAGE_B)       // 147456
#define TILE_W   4608                // words per tile

template<int EPI, int CMASK, int CKLIM>
__global__ void __launch_bounds__(256, 1)
gemm_mma(const bf16* __restrict__ Ahp, const bf16* __restrict__ Alp,
         const bf16* __restrict__ Bhp, const bf16* __restrict__ Blp,
         const float* __restrict__ R,
         float* __restrict__ Cf, bf16* __restrict__ Ch, bf16* __restrict__ Cl,
         int Ntot, int Ktot, int ldC)
{
    const int row0 = blockIdx.y * 128;
    const int col0 = blockIdx.x * 128;
    if (CMASK && col0 > row0 + 127) return;

    extern __shared__ __align__(16) char smem_raw[];
    const uint32_t sbase = smem_u32(smem_raw);

    const int tid  = threadIdx.x;
    const int lane = tid & 31;
    const int wid  = tid >> 5;
    const int wm   = (wid & 1) * 64;
    const int wn   = (wid >> 1) * 32;
    const int gr   = lane >> 2;
    const int lc   = lane & 3;

    int nch = Ktot >> 6;
    if (CKLIM) { int lim = (row0 + 128) >> 6; nch = (lim < nch) ? lim : nch; }

    float acc[4][4][4] = {};

    // ---- loader: one 64-wide K chunk into stage stg ----
    const int ldr  = tid >> 1;        // 0..127 row
    const int lhf  = tid & 1;         // half-row (64B = 4 x 16B)
    auto issue = [&](int ch, int stg) {
        const size_t ko = (size_t)(ch << 6) + (lhf << 5);
        uint32_t dst = sbase + stg * STAGE_B + ldr * 144 + lhf * 64;
        const bf16* s0 = Ahp + (size_t)(row0 + ldr) * Ktot + ko;
        const bf16* s1 = Alp + (size_t)(row0 + ldr) * Ktot + ko;
        const bf16* s2 = Bhp + (size_t)(col0 + ldr) * Ktot + ko;
        const bf16* s3 = Blp + (size_t)(col0 + ldr) * Ktot + ko;
#pragma unroll
        for (int i = 0; i < 4; i++) CP16(dst + i * 16,            s0 + i * 8);
#pragma unroll
        for (int i = 0; i < 4; i++) CP16(dst + TILE_B + i * 16,   s1 + i * 8);
#pragma unroll
        for (int i = 0; i < 4; i++) CP16(dst + 2*TILE_B + i * 16, s2 + i * 8);
#pragma unroll
        for (int i = 0; i < 4; i++) CP16(dst + 3*TILE_B + i * 16, s3 + i * 8);
        CP_COMMIT();
    };

    issue(0, 0);
    if (nch > 1) issue(1, 1);

    const uint32_t* Sw = (const uint32_t*)smem_raw;

    for (int ch = 0; ch < nch; ch++) {
        if (ch + 1 < nch) CP_WAIT1(); else CP_WAIT0();
        __syncthreads();

        const int stg = ch & 1;
        const uint32_t* As  = Sw + stg * (STAGE_B / 4);
        const uint32_t* Als = As + TILE_W;
        const uint32_t* Bs  = As + 2 * TILE_W;
        const uint32_t* Bls = As + 3 * TILE_W;

#pragma unroll
        for (int ks = 0; ks < 4; ks++) {
            const int kb = ks * 8 + lc;
            uint32_t ah[4][4], al[4][4], bh[4][2], bl[4][2];
#pragma unroll
            for (int mt = 0; mt < 4; mt++) {
                int r0 = (wm + mt * 16 + gr) * 36 + kb;
                ah[mt][0] = As [r0];        ah[mt][1] = As [r0 + 288];
                ah[mt][2] = As [r0 + 4];    ah[mt][3] = As [r0 + 292];
                al[mt][0] = Als[r0];        al[mt][1] = Als[r0 + 288];
                al[mt][2] = Als[r0 + 4];    al[mt][3] = Als[r0 + 292];
            }
#pragma unroll
            for (int nt = 0; nt < 4; nt++) {
                int r0 = (wn + nt * 8 + gr) * 36 + kb;
                bh[nt][0] = Bs [r0];  bh[nt][1] = Bs [r0 + 4];
                bl[nt][0] = Bls[r0];  bl[nt][1] = Bls[r0 + 4];
            }
#pragma unroll
            for (int mt = 0; mt < 4; mt++)
#pragma unroll
                for (int nt = 0; nt < 4; nt++) {
                    mma16816(acc[mt][nt], ah[mt], bh[nt]);
                    mma16816(acc[mt][nt], al[mt], bh[nt]);
                    mma16816(acc[mt][nt], ah[mt], bl[nt]);
                }
        }

        if (ch + 2 < nch) {
            __syncthreads();
            issue(ch + 2, stg);
        }
    }

    // ---------------- epilogue -------------------------------------------------
    if (EPI <= 3) {
#pragma unroll
        for (int mt = 0; mt < 4; mt++)
#pragma unroll
            for (int nt = 0; nt < 4; nt++) {
                const int ri = wm + mt * 16 + gr;
                const int ci = wn + nt * 8 + 2 * lc;
#pragma unroll
                for (int hf = 0; hf < 2; hf++) {
                    const int r = row0 + ri + hf * 8;
                    const int c = col0 + ci;
                    float v0 = acc[mt][nt][hf * 2 + 0];
                    float v1 = acc[mt][nt][hf * 2 + 1];
                    if (EPI == 2) { v0 = fmaxf(v0, 0.f); v1 = fmaxf(v1, 0.f); }
                    if (EPI == 3) {
                        float2 rv = *(const float2*)&R[(size_t)r * Ntot + c];
                        v0 += rv.x; v1 += rv.y;
                        *(float2*)&Cf[(size_t)r * ldC + c] = make_float2(v0, v1);
                    }
                    if (EPI == 0) {
                        *(float2*)&Cf[(size_t)r * ldC + c] = make_float2(v0, v1);
                    } else {
                        bf16 h0, l0, h1, l1;
                        split2(v0, h0, l0); split2(v1, h1, l1);
                        *(__nv_bfloat162*)&Ch[(size_t)r * ldC + c] =
                            __nv_bfloat162(h0, h1);
                        *(__nv_bfloat162*)&Cl[(size_t)r * ldC + c] =
                            __nv_bfloat162(l0, l1);
                    }
                }
            }
    } else {
        // transposed epilogues via fp32 smem buffer [128][130]
        __syncthreads();
        float* Tb = (float*)smem_raw;
#pragma unroll
        for (int mt = 0; mt < 4; mt++)
#pragma unroll
            for (int nt = 0; nt < 4; nt++) {
                const int ri = wm + mt * 16 + gr;
                const int ci = wn + nt * 8 + 2 * lc;
#pragma unroll
                for (int hf = 0; hf < 2; hf++) {
                    const int rr = ri + hf * 8;
                    float v0 = acc[mt][nt][hf * 2 + 0];
                    float v1 = acc[mt][nt][hf * 2 + 1];
                    if (EPI == 5) {
                        float2 rv = *(const float2*)
                            &R[(size_t)(row0 + rr) * Ntot + col0 + ci];
                        v0 += rv.x; v1 += rv.y;
                    }
                    Tb[rr * 130 + ci]     = v0;
                    Tb[rr * 130 + ci + 1] = v1;
                }
            }
        __syncthreads();
        const int j  = tid & 127;          // output row index within tile = GEMM col
        const int sg = tid >> 7;           // half of the 128 GEMM rows
        const int rb = sg * 64;
        if (EPI == 4) {
#pragma unroll
            for (int g = 0; g < 8; g++) {
                uint32_t hp[4], lp[4];
#pragma unroll
                for (int e = 0; e < 4; e++) {
                    float v0 = Tb[(rb + g * 8 + 2 * e)     * 130 + j];
                    float v1 = Tb[(rb + g * 8 + 2 * e + 1) * 130 + j];
                    bf16 h0, l0, h1, l1;
                    split2(v0, h0, l0); split2(v1, h1, l1);
                    __nv_bfloat162 hh(h0, h1), ll(l0, l1);
                    hp[e] = *(uint32_t*)&hh; lp[e] = *(uint32_t*)&ll;
                }
                size_t o = (size_t)(col0 + j) * ldC + row0 + rb + g * 8;
                *(uint4*)&Ch[o] = make_uint4(hp[0], hp[1], hp[2], hp[3]);
                *(uint4*)&Cl[o] = make_uint4(lp[0], lp[1], lp[2], lp[3]);
            }
        } else {  // EPI 5
#pragma unroll
            for (int g = 0; g < 16; g++) {
                float4 v;
                v.x = Tb[(rb + g * 4 + 0) * 130 + j];
                v.y = Tb[(rb + g * 4 + 1) * 130 + j];
                v.z = Tb[(rb + g * 4 + 2) * 130 + j];
                v.w = Tb[(rb + g * 4 + 3) * 130 + j];
                *(float4*)&Cf[(size_t)(col0 + j) * ldC + row0 + rb + g * 4] = v;
            }
        }
    }
}

// ---------------- transpose + bf16 split -------------------------------------
// in [Rr][Cc] row-major -> out [Cc][Rr]: oh/ol bf16 (+ of fp32 if non-null)
__global__ __launch_bounds__(256)
void tsplit(const float* __restrict__ in, bf16* __restrict__ oh,
            bf16* __restrict__ ol, float* __restrict__ of, int Rr, int Cc)
{
    __shared__ float t[32][33];
    int x = blockIdx.x * 32 + threadIdx.x;
    int y = blockIdx.y * 32 + threadIdx.y;
#pragma unroll
    for (int i = 0; i < 32; i += 8)
        t[threadIdx.y + i][threadIdx.x] = in[(size_t)(y + i) * Cc + x];
    __syncthreads();
    int xo = blockIdx.y * 32 + threadIdx.x;
    int yo = blockIdx.x * 32 + threadIdx.y;
#pragma unroll
    for (int i = 0; i < 32; i += 8) {
        float v = t[threadIdx.x][threadIdx.y + i];
        size_t o = (size_t)(yo + i) * Rr + xo;
        bf16 h, l; split2(v, h, l);
        oh[o] = h; ol[o] = l;
        if (of) of[o] = v;
    }
}

// ---------------- causal softmax -> bf16 split A -----------------------------
__global__ __launch_bounds__(256)
void softmax_split(const float* __restrict__ S, bf16* __restrict__ Ah,
                   bf16* __restrict__ Al)
{
    const int row = blockIdx.x;
    const int len = row + 1;
    __shared__ float buf[NTOK];
    __shared__ float red[256];
    const int tid = threadIdx.x;
    const float* p = S + (size_t)row * NTOK;

    float m = NEG_INF;
    for (int j = tid; j < len; j += 256) { float v = p[j]; buf[j] = v; m = fmaxf(m, v); }
    red[tid] = m; __syncthreads();
    for (int s = 128; s > 0; s >>= 1) {
        if (tid < s) red[tid] = fmaxf(red[tid], red[tid + s]);
        __syncthreads();
    }
    m = red[0]; __syncthreads();

    float sum = 0.f;
    for (int j = tid; j < len; j += 256) { float e = __expf(buf[j] - m); buf[j] = e; sum += e; }
    red[tid] = sum; __syncthreads();
    for (int s = 128; s > 0; s >>= 1) {
        if (tid < s) red[tid] += red[tid + s];
        __syncthreads();
    }
    const float inv = 1.f / red[0];

    const int be = ((row >> 7) + 1) << 7;   // zero-fill to row-block end for CKLIM
    for (int j = tid; j < be; j += 256) {
        float v = (j < len) ? buf[j] * inv : 0.f;
        bf16 h, l; split2(v, h, l);
        size_t o = (size_t)row * NTOK + j;
        Ah[o] = h; Al[o] = l;
    }
}

// ---------------- driver ------------------------------------------------------
extern "C" void kernel_launch(void* const* d_in, const int* in_sizes, int n_in,
                              void* d_out, int out_size) {
    (void)in_sizes; (void)n_in; (void)out_size;
    const float* X    = (const float*)d_in[0];
    const float* W[6] = {(const float*)d_in[1], (const float*)d_in[2],
                         (const float*)d_in[3], (const float*)d_in[4],
                         (const float*)d_in[5], (const float*)d_in[6]};
    float* out = (float*)d_out;

    float *Xt, *S, *X2;
    bf16 *Xth, *Xtl, *Wth, *Wtl, *Qh, *Ql, *Kh, *Kl, *Vh, *Vl;
    bf16 *RHth, *RHtl, *Ah, *Al, *X2h, *X2l, *Hh, *Hl;
    cudaGetSymbolAddress((void**)&Xt,  g_Xt);   cudaGetSymbolAddress((void**)&Xth, g_Xth);
    cudaGetSymbolAddress((void**)&Xtl, g_Xtl);  cudaGetSymbolAddress((void**)&Wth, g_Wth);
    cudaGetSymbolAddress((void**)&Wtl, g_Wtl);  cudaGetSymbolAddress((void**)&Qh,  g_Qh);
    cudaGetSymbolAddress((void**)&Ql,  g_Ql);   cudaGetSymbolAddress((void**)&Kh,  g_Kh);
    cudaGetSymbolAddress((void**)&Kl,  g_Kl);   cudaGetSymbolAddress((void**)&Vh,  g_Vh);
    cudaGetSymbolAddress((void**)&Vl,  g_Vl);   cudaGetSymbolAddress((void**)&RHth, g_RHth);
    cudaGetSymbolAddress((void**)&RHtl, g_RHtl); cudaGetSymbolAddress((void**)&S,  g_S);
    cudaGetSymbolAddress((void**)&Ah,  g_Ah);   cudaGetSymbolAddress((void**)&Al,  g_Al);
    cudaGetSymbolAddress((void**)&X2,  g_X2);   cudaGetSymbolAddress((void**)&X2h, g_X2h);
    cudaGetSymbolAddress((void**)&X2l, g_X2l);  cudaGetSymbolAddress((void**)&Hh,  g_Hh);
    cudaGetSymbolAddress((void**)&Hl,  g_Hl);

    cudaFuncSetAttribute(gemm_mma<0,1,0>, cudaFuncAttributeMaxDynamicSharedMemorySize, DSMEM);
    cudaFuncSetAttribute(gemm_mma<1,0,0>, cudaFuncAttributeMaxDynamicSharedMemorySize, DSMEM);
    cudaFuncSetAttribute(gemm_mma<2,0,0>, cudaFuncAttributeMaxDynamicSharedMemorySize, DSMEM);
    cudaFuncSetAttribute(gemm_mma<3,0,1>, cudaFuncAttributeMaxDynamicSharedMemorySize, DSMEM);
    cudaFuncSetAttribute(gemm_mma<4,0,0>, cudaFuncAttributeMaxDynamicSharedMemorySize, DSMEM);
    cudaFuncSetAttribute(gemm_mma<5,0,0>, cudaFuncAttributeMaxDynamicSharedMemorySize, DSMEM);

    dim3 tb(32, 8);
    tsplit<<<dim3(NTOK / 32, DM / 32), tb>>>(X, Xth, Xtl, Xt, DM, NTOK);
    for (int i = 0; i < 6; i++)
        tsplit<<<dim3(DM / 32, DM / 32), tb>>>(W[i], Wth + (size_t)i * DM * DM,
                                               Wtl + (size_t)i * DM * DM, nullptr, DM, DM);

    const size_t WSZ = (size_t)DM * DM;
    dim3 blk(256);
    dim3 grid_d(DM / 128, NTOK / 128);     // 8 x 32
    dim3 grid_s(NTOK / 128, NTOK / 128);   // 32 x 32

    // Q, K, V projections -> bf16 hi/lo
    gemm_mma<1,0,0><<<grid_d, blk, DSMEM>>>(Xth, Xtl, Wth + 0*WSZ, Wtl + 0*WSZ,
                                            nullptr, nullptr, Qh, Ql, DM, DM, DM);
    gemm_mma<1,0,0><<<grid_d, blk, DSMEM>>>(Xth, Xtl, Wth + 1*WSZ, Wtl + 1*WSZ,
                                            nullptr, nullptr, Kh, Kl, DM, DM, DM);
    gemm_mma<1,0,0><<<grid_d, blk, DSMEM>>>(Xth, Xtl, Wth + 2*WSZ, Wtl + 2*WSZ,
                                            nullptr, nullptr, Vh, Vl, DM, DM, DM);
    // RH^T = (V @ W_O)^T  (transposed hi/lo store)
    gemm_mma<4,0,0><<<grid_d, blk, DSMEM>>>(Vh, Vl, Wth + 3*WSZ, Wtl + 3*WSZ,
                                            nullptr, nullptr, RHth, RHtl, DM, DM, NTOK);
    // scores = Q @ K^T (upper tiles skipped; masked entries never read)
    gemm_mma<0,1,0><<<grid_s, blk, DSMEM>>>(Qh, Ql, Kh, Kl,
                                            nullptr, S, nullptr, nullptr, NTOK, DM, NTOK);
    // softmax rows -> A hi/lo (zero-filled to 128-block end)
    softmax_split<<<NTOK, 256>>>(S, Ah, Al);
    // X2 = Xt + A @ RH  (K bounded by causality)
    gemm_mma<3,0,1><<<grid_d, blk, DSMEM>>>(Ah, Al, RHth, RHtl,
                                            Xt, X2, X2h, X2l, DM, NTOK, DM);
    // H = relu(X2 @ mlp_in)
    gemm_mma<2,0,0><<<grid_d, blk, DSMEM>>>(X2h, X2l, Wth + 4*WSZ, Wtl + 4*WSZ,
                                            nullptr, nullptr, Hh, Hl, DM, DM, DM);
    // out = (X2 + H @ mlp_out)^T
    gemm_mma<5,0,0><<<grid_d, blk, DSMEM>>>(Hh, Hl, Wth + 5*WSZ, Wtl + 5*WSZ,
                                            X2, out, nullptr, nullptr, DM, DM, NTOK);
}